// round 11
// baseline (speedup 1.0000x reference)
#include <cuda_runtime.h>
#include <cuda_fp16.h>
#include <math.h>
#include <stdint.h>

// Problem constants
#define T_TOK 8192
#define DIM   1024
#define NEXP  8
#define HID   4096
#define MTILE 128
#define MAXROWS 17408            // 16384 + 8*128 pad
#define MAXMT   (MAXROWS / MTILE)

// ---------------- device scratch (static; no cudaMalloc) -------------------
__device__ __half g_xh [(size_t)T_TOK * DIM];      // LN out fp16 (GEMM1 A)
__device__ __half g_hh [(size_t)MAXROWS * HID];    // gelu(x@W1+b1) fp16
__device__ __half g_w1h[(size_t)NEXP * DIM * HID]; // W1 -> [e][n(H)][k(D)] fp16
__device__ __half g_w2h[(size_t)NEXP * HID * DIM]; // W2 -> [e][n(D)][k(H)] fp16
__device__ int    g_perm[MAXROWS];                 // permuted row -> token
__device__ float  g_gwrow[MAXROWS];                // permuted row -> gate weight
__device__ float  g_gw  [T_TOK * 2];
__device__ int    g_gi  [T_TOK * 2];
__device__ int    g_counts[NEXP];
__device__ int    g_off[NEXP + 1];
__device__ int    g_cursor[NEXP];

// ---------------- helpers ----------------------------------------------------
__device__ __forceinline__ void mma_f16(float* c, const unsigned* a, const unsigned* b) {
    asm volatile(
        "mma.sync.aligned.m16n8k16.row.col.f32.f16.f16.f32 "
        "{%0,%1,%2,%3}, {%4,%5,%6,%7}, {%8,%9}, {%0,%1,%2,%3};\n"
        : "+f"(c[0]), "+f"(c[1]), "+f"(c[2]), "+f"(c[3])
        : "r"(a[0]), "r"(a[1]), "r"(a[2]), "r"(a[3]), "r"(b[0]), "r"(b[1]));
}

__device__ __forceinline__ void ldsm_x4(unsigned& r0, unsigned& r1, unsigned& r2, unsigned& r3,
                                        uint32_t addr) {
    asm volatile("ldmatrix.sync.aligned.m8n8.x4.shared.b16 {%0,%1,%2,%3}, [%4];"
        : "=r"(r0), "=r"(r1), "=r"(r2), "=r"(r3) : "r"(addr));
}

__device__ __forceinline__ void cp_async16(uint32_t saddr, const void* gptr) {
    asm volatile("cp.async.cg.shared.global [%0], [%1], 16;"
        :: "r"(saddr), "l"(__cvta_generic_to_global(gptr)) : "memory");
}
#define CP_COMMIT() asm volatile("cp.async.commit_group;" ::: "memory")
#define CP_WAIT2()  asm volatile("cp.async.wait_group 2;"  ::: "memory")
#define CP_WAIT0()  asm volatile("cp.async.wait_group 0;"  ::: "memory")

// ---------------- out = x (residual pre-init for fused combine) -------------
__global__ void initout_kernel(const float* __restrict__ x, float* __restrict__ out) {
    int i = blockIdx.x * blockDim.x + threadIdx.x;
    reinterpret_cast<float4*>(out)[i] = reinterpret_cast<const float4*>(x)[i];
}

// ---------------- weight transpose+fp16: [e][k][n] f32 -> [e][n][k] f16 -----
__global__ void transpose_h_kernel(const float* __restrict__ in, __half* __restrict__ out,
                                   int K, int N) {
    __shared__ float t[32][33];
    const size_t eo = (size_t)blockIdx.z * K * N;
    const int n0 = blockIdx.x * 32, k0 = blockIdx.y * 32;
    for (int j = threadIdx.y; j < 32; j += 8)
        t[j][threadIdx.x] = in[eo + (size_t)(k0 + j) * N + n0 + threadIdx.x];
    __syncthreads();
    for (int j = threadIdx.y; j < 32; j += 8)
        out[eo + (size_t)(n0 + j) * K + k0 + threadIdx.x] = __float2half_rn(t[threadIdx.x][j]);
}

// ---------------- Fused LayerNorm + gating (no global atomics) --------------
__global__ void ln_gate_kernel(const float* __restrict__ x,
                               const float* __restrict__ gamma,
                               const float* __restrict__ beta,
                               const float* __restrict__ gate_w) {
    int t = blockIdx.x;
    int tid = threadIdx.x;
    int lane = tid & 31, wrp = tid >> 5;
    const float4 v = *reinterpret_cast<const float4*>(x + (size_t)t * DIM + tid * 4);
    __shared__ float red1[8], red2[8];
    __shared__ float sgate[8][8];
    __shared__ float slog[8];

    float s = v.x + v.y + v.z + v.w;
    #pragma unroll
    for (int o = 16; o; o >>= 1) s += __shfl_xor_sync(0xffffffffu, s, o);
    if (lane == 0) red1[wrp] = s;
    __syncthreads();
    float mu = 0.f;
    #pragma unroll
    for (int i = 0; i < 8; i++) mu += red1[i];
    mu *= (1.f / DIM);

    float dx = v.x - mu, dy = v.y - mu, dz = v.z - mu, dw = v.w - mu;
    float s2 = dx * dx + dy * dy + dz * dz + dw * dw;
    #pragma unroll
    for (int o = 16; o; o >>= 1) s2 += __shfl_xor_sync(0xffffffffu, s2, o);
    if (lane == 0) red2[wrp] = s2;
    __syncthreads();
    float var = 0.f;
    #pragma unroll
    for (int i = 0; i < 8; i++) var += red2[i];
    var *= (1.f / DIM);
    float rstd = rsqrtf(var + 1e-5f);

    const float4 g = *reinterpret_cast<const float4*>(gamma + tid * 4);
    const float4 b = *reinterpret_cast<const float4*>(beta  + tid * 4);
    float4 o;
    o.x = dx * rstd * g.x + b.x;
    o.y = dy * rstd * g.y + b.y;
    o.z = dz * rstd * g.z + b.z;
    o.w = dw * rstd * g.w + b.w;

    __half2 h0 = __floats2half2_rn(o.x, o.y);
    __half2 h1 = __floats2half2_rn(o.z, o.w);
    *reinterpret_cast<__half2*>(g_xh + (size_t)t * DIM + tid * 4)     = h0;
    *reinterpret_cast<__half2*>(g_xh + (size_t)t * DIM + tid * 4 + 2) = h1;

    float accg[NEXP];
    #pragma unroll
    for (int e = 0; e < NEXP; e++) {
        const float4 w = *reinterpret_cast<const float4*>(gate_w + e * DIM + tid * 4);
        accg[e] = o.x * w.x + o.y * w.y + o.z * w.z + o.w * w.w;
    }
    #pragma unroll
    for (int e = 0; e < NEXP; e++)
        #pragma unroll
        for (int off = 16; off; off >>= 1)
            accg[e] += __shfl_xor_sync(0xffffffffu, accg[e], off);
    if (lane == 0)
        #pragma unroll
        for (int e = 0; e < NEXP; e++) sgate[wrp][e] = accg[e];
    __syncthreads();
    if (tid < NEXP) {
        float l = 0.f;
        #pragma unroll
        for (int w = 0; w < 8; w++) l += sgate[w][tid];
        slog[tid] = l;
    }
    __syncthreads();
    if (tid == 0) {
        int i0 = 0; float v0 = slog[0];
        #pragma unroll
        for (int e = 1; e < NEXP; e++) if (slog[e] > v0) { v0 = slog[e]; i0 = e; }
        int i1 = -1; float v1 = -3.0e38f;
        #pragma unroll
        for (int e = 0; e < NEXP; e++) if (e != i0 && slog[e] > v1) { v1 = slog[e]; i1 = e; }
        float ex = expf(v1 - v0);
        float g0 = 1.f / (1.f + ex);
        float g1 = ex / (1.f + ex);
        g_gi[2 * t]     = i0;  g_gi[2 * t + 1] = i1;
        g_gw[2 * t]     = g0;  g_gw[2 * t + 1] = g1;
    }
}

// ---------------- Scan: histogram g_gi + padded offsets (one block) ---------
__global__ void scan_kernel() {
    __shared__ int cnt[NEXP];
    int tid = threadIdx.x;
    if (tid < NEXP) cnt[tid] = 0;
    __syncthreads();
    for (int i = tid; i < 2 * T_TOK; i += 256)
        atomicAdd(&cnt[g_gi[i]], 1);
    __syncthreads();
    if (tid == 0) {
        int o = 0;
        for (int e = 0; e < NEXP; e++) {
            g_counts[e] = cnt[e];
            g_off[e] = o;
            g_cursor[e] = o;
            o += ((cnt[e] + (MTILE - 1)) / MTILE) * MTILE;
        }
        g_off[NEXP] = o;
    }
}

__global__ void scatter_kernel() {
    int t = blockIdx.x * blockDim.x + threadIdx.x;
    if (t >= T_TOK) return;
    #pragma unroll
    for (int s = 0; s < 2; s++) {
        int e = g_gi[2 * t + s];
        int pos = atomicAdd(&g_cursor[e], 1);
        g_perm[pos]  = t;
        g_gwrow[pos] = g_gw[2 * t + s];
    }
}

// ---------------- Grouped GEMM: fp16 mma m16n8k16 + ldmatrix, 4-stage -------
// Tile 128x128x32, 8 warps (4M x 2N), warp tile 32x64, 4-stage cp.async.
#define NSTAGE 4
#define LSTRIDE 40                       // halves per row (80B)
#define A_STAGE_H (128 * LSTRIDE)
#define B_STAGE_H (128 * LSTRIDE)
#define B_BASE_H  (NSTAGE * A_STAGE_H)
#define SMEM_H    (NSTAGE * A_STAGE_H + NSTAGE * B_STAGE_H)
#define SMEM_GEMM_BYTES (SMEM_H * 2)
#define A_STAGE_B (A_STAGE_H * 2)
#define B_STAGE_B (B_STAGE_H * 2)
#define B_BASE_B  (B_BASE_H * 2)
#define CSTRIDE 136                      // halves per staged C row (272B)

// MODE 1: A = gather(g_xh, perm) [K=1024], B = g_w1h, C = gelu(.+b1) -> g_hh
//         (C staged in SMEM, written out coalesced)
// MODE 2: A = g_hh rows          [K=4096], B = g_w2h,
//         C scattered: atomicAdd(out[tok], gate_w * (.+b2))  [fused combine]
template <int MODE>
__global__ void __launch_bounds__(256, 2)
gemm_mma(const __half* __restrict__ Bw, const float* __restrict__ bias,
         float* __restrict__ outp, int Kdim, int Ncols) {
    extern __shared__ __align__(16) __half smh[];

    const int base = blockIdx.y * MTILE;
    if (base >= g_off[NEXP]) return;
    int e = 0;
    while (base >= g_off[e + 1]) e++;
    const int rows_valid = g_off[e] + g_counts[e] - base;
    if (rows_valid <= 0) return;

    const int tid  = threadIdx.x;
    const int lane = tid & 31;
    const int wid  = tid >> 5;
    const int wm = wid & 3;
    const int wn = wid >> 2;
    const int g8   = lane >> 2;
    const int ctid = lane & 3;

    const int ncolbase = blockIdx.x * 128;

    // ---- gmem loaders: 2 threads per row; 2 x 16B segs each per chunk
    const int lrow  = tid >> 1;
    const int lseg  = (tid & 1) * 2;

    const __half* asrc;
    if (MODE == 1) {
        int tok = g_perm[base + lrow];
        if (tok < 0) tok = 0;
        asrc = g_xh + (size_t)tok * DIM;
    } else {
        asrc = g_hh + (size_t)(base + lrow) * HID;
    }
    const __half* bsrc = Bw + ((size_t)e * Ncols + ncolbase + lrow) * Kdim;

    const uint32_t smem_u32 = (uint32_t)__cvta_generic_to_shared(smh);
    const uint32_t a_off0 = lrow * (LSTRIDE * 2) + lseg * 16;
    const uint32_t b_off0 = B_BASE_B + lrow * (LSTRIDE * 2) + lseg * 16;

    // ---- ldmatrix per-thread offsets (bytes)
    const int mq = lane >> 3;
    const int r7 = lane & 7;
    const uint32_t aoff = ((wm * 32 + ((mq & 1) << 3) + r7) * LSTRIDE + ((mq >> 1) << 3)) * 2;
    const uint32_t boff = B_BASE_B +
        ((wn * 64 + ((mq >> 1) << 3) + r7) * LSTRIDE + ((mq & 1) << 3)) * 2;

    float acc[2][8][4];
    #pragma unroll
    for (int i = 0; i < 2; i++)
        #pragma unroll
        for (int j = 0; j < 8; j++)
            #pragma unroll
            for (int q = 0; q < 4; q++) acc[i][j][q] = 0.f;

    const int nch = Kdim / 32;

    // prologue: stage chunks 0..NSTAGE-2
    #pragma unroll
    for (int s = 0; s < NSTAGE - 1; s++) {
        const __half* ga = asrc + s * 32 + lseg * 8;
        const __half* gb = bsrc + s * 32 + lseg * 8;
        const uint32_t ao = smem_u32 + s * A_STAGE_B + a_off0;
        const uint32_t bo = smem_u32 + s * B_STAGE_B + b_off0;
        cp_async16(ao,      ga);
        cp_async16(ao + 16, ga + 8);
        cp_async16(bo,      gb);
        cp_async16(bo + 16, gb + 8);
        CP_COMMIT();
    }

    for (int kc = 0; kc < nch; kc++) {
        CP_WAIT2();
        __syncthreads();

        const int cl = kc + NSTAGE - 1;
        if (cl < nch) {
            const int st2 = cl % NSTAGE;
            const __half* ga = asrc + cl * 32 + lseg * 8;
            const __half* gb = bsrc + cl * 32 + lseg * 8;
            const uint32_t ao = smem_u32 + st2 * A_STAGE_B + a_off0;
            const uint32_t bo = smem_u32 + st2 * B_STAGE_B + b_off0;
            cp_async16(ao,      ga);
            cp_async16(ao + 16, ga + 8);
            cp_async16(bo,      gb);
            cp_async16(bo + 16, gb + 8);
        }
        CP_COMMIT();

        const int st = kc % NSTAGE;
        const uint32_t aBase = smem_u32 + st * A_STAGE_B + aoff;
        const uint32_t bBase = smem_u32 + st * B_STAGE_B + boff;

        #pragma unroll
        for (int ks = 0; ks < 2; ks++) {
            unsigned afr[2][4], bfr[8][2];
            #pragma unroll
            for (int i = 0; i < 2; i++)
                ldsm_x4(afr[i][0], afr[i][1], afr[i][2], afr[i][3],
                        aBase + i * (16 * LSTRIDE * 2) + ks * 32);
            #pragma unroll
            for (int jp = 0; jp < 4; jp++) {
                unsigned r0, r1, r2, r3;
                ldsm_x4(r0, r1, r2, r3, bBase + jp * (16 * LSTRIDE * 2) + ks * 32);
                bfr[2 * jp][0] = r0; bfr[2 * jp][1] = r1;
                bfr[2 * jp + 1][0] = r2; bfr[2 * jp + 1][1] = r3;
            }
            #pragma unroll
            for (int i = 0; i < 2; i++)
                #pragma unroll
                for (int j = 0; j < 8; j++)
                    mma_f16(acc[i][j], afr[i], bfr[j]);
        }
    }
    CP_WAIT0();

    // ---- epilogue
    if (MODE == 1) {
        // stage C tile in SMEM (conflict-free), then coalesced writeout
        __syncthreads();   // mainloop smem reads complete before overwrite
        #pragma unroll
        for (int i = 0; i < 2; i++) {
            const int r0 = wm * 32 + i * 16 + g8;
            #pragma unroll
            for (int j = 0; j < 8; j++) {
                const int c = wn * 64 + j * 8 + ctid * 2;
                const int ng = ncolbase + c;
                const float bv0 = bias[ng], bv1 = bias[ng + 1];
                float v0 = acc[i][j][0] + bv0;
                float v1 = acc[i][j][1] + bv1;
                v0 *= normcdff(v0); v1 *= normcdff(v1);
                *reinterpret_cast<__half2*>(smh + (size_t)r0 * CSTRIDE + c) =
                    __floats2half2_rn(v0, v1);
                float v2 = acc[i][j][2] + bv0;
                float v3 = acc[i][j][3] + bv1;
                v2 *= normcdff(v2); v3 *= normcdff(v3);
                *reinterpret_cast<__half2*>(smh + (size_t)(r0 + 8) * CSTRIDE + c) =
                    __floats2half2_rn(v2, v3);
            }
        }
        __syncthreads();
        const int row  = tid >> 1;
        const int halfo = (tid & 1) * 64;   // halves
        if (row < rows_valid) {
            const int pos = base + row;
            const uint4* src = reinterpret_cast<const uint4*>(smh + (size_t)row * CSTRIDE + halfo);
            uint4* dst = reinterpret_cast<uint4*>(g_hh + (size_t)pos * HID + ncolbase + halfo);
            #pragma unroll
            for (int i = 0; i < 8; i++) dst[i] = src[i];
        }
    } else {
        #pragma unroll
        for (int i = 0; i < 2; i++) {
            const int r0 = wm * 32 + i * 16 + g8;
            const int pos0 = base + r0;
            const int pos1 = base + r0 + 8;
            int   tok0 = 0, tok1 = 0;
            float gw0 = 0.f, gw1 = 0.f;
            if (r0 < rows_valid)     { tok0 = g_perm[pos0]; gw0 = g_gwrow[pos0]; }
            if (r0 + 8 < rows_valid) { tok1 = g_perm[pos1]; gw1 = g_gwrow[pos1]; }
            #pragma unroll
            for (int j = 0; j < 8; j++) {
                const int c = wn * 64 + j * 8 + ctid * 2;
                const int ng = ncolbase + c;
                const float bv0 = bias[ng], bv1 = bias[ng + 1];
                if (r0 < rows_valid) {
                    atomicAdd(&outp[(size_t)tok0 * DIM + ng],     gw0 * (acc[i][j][0] + bv0));
                    atomicAdd(&outp[(size_t)tok0 * DIM + ng + 1], gw0 * (acc[i][j][1] + bv1));
                }
                if (r0 + 8 < rows_valid) {
                    atomicAdd(&outp[(size_t)tok1 * DIM + ng],     gw1 * (acc[i][j][2] + bv0));
                    atomicAdd(&outp[(size_t)tok1 * DIM + ng + 1], gw1 * (acc[i][j][3] + bv1));
                }
            }
        }
    }
}

// ---------------- Balance loss -------------------------------------------------
__global__ void loss_kernel(float* __restrict__ out, int out_size) {
    __shared__ float red[256];
    __shared__ float tot[NEXP];
    int tid = threadIdx.x;
    float s[NEXP];
    #pragma unroll
    for (int q = 0; q < NEXP; q++) s[q] = 0.f;
    for (int i = tid; i < 2 * T_TOK; i += 256) {
        int e = g_gi[i];
        float w = g_gw[i];
        #pragma unroll
        for (int q = 0; q < NEXP; q++) s[q] += (e == q) ? w : 0.f;
    }
    for (int q = 0; q < NEXP; q++) {
        red[tid] = s[q];
        __syncthreads();
        for (int o = 128; o; o >>= 1) {
            if (tid < o) red[tid] += red[tid + o];
            __syncthreads();
        }
        if (tid == 0) tot[q] = red[0];
        __syncthreads();
    }
    if (tid == 0 && out_size > T_TOK * DIM) {
        float l = 0.f;
        #pragma unroll
        for (int q = 0; q < NEXP; q++) {
            float d = tot[q] * (1.f / T_TOK) - (1.f / NEXP);
            l += d * d;
        }
        out[T_TOK * DIM] = l * (1.f / NEXP);
    }
}

// ---------------- launch --------------------------------------------------------
extern "C" void kernel_launch(void* const* d_in, const int* in_sizes, int n_in,
                              void* d_out, int out_size) {
    const float* x      = (const float*)d_in[0];
    const float* gamma  = (const float*)d_in[1];
    const float* beta   = (const float*)d_in[2];
    const float* gate_w = (const float*)d_in[3];
    const float* W1     = (const float*)d_in[4];
    const float* b1     = (const float*)d_in[5];
    const float* W2     = (const float*)d_in[6];
    const float* b2     = (const float*)d_in[7];
    float* out = (float*)d_out;

    cudaFuncSetAttribute(gemm_mma<1>, cudaFuncAttributeMaxDynamicSharedMemorySize, SMEM_GEMM_BYTES);
    cudaFuncSetAttribute(gemm_mma<2>, cudaFuncAttributeMaxDynamicSharedMemorySize, SMEM_GEMM_BYTES);

    __half *w1h, *w2h;
    cudaGetSymbolAddress((void**)&w1h, g_w1h);
    cudaGetSymbolAddress((void**)&w2h, g_w2h);

    // one-time stream/event setup (no device memory; deterministic)
    static cudaStream_t s2 = nullptr;
    static cudaEvent_t eFork = nullptr, eW1 = nullptr, eW2 = nullptr;
    if (!s2) {
        cudaStreamCreateWithFlags(&s2, cudaStreamNonBlocking);
        cudaEventCreateWithFlags(&eFork, cudaEventDisableTiming);
        cudaEventCreateWithFlags(&eW1,   cudaEventDisableTiming);
        cudaEventCreateWithFlags(&eW2,   cudaEventDisableTiming);
    }

    // ---- fork: weight prep + out-init on side stream ------------------------
    cudaEventRecord(eFork, 0);
    cudaStreamWaitEvent(s2, eFork, 0);
    transpose_h_kernel<<<dim3(HID / 32, DIM / 32, NEXP), dim3(32, 8), 0, s2>>>(W1, w1h, DIM, HID);
    cudaEventRecord(eW1, s2);
    transpose_h_kernel<<<dim3(DIM / 32, HID / 32, NEXP), dim3(32, 8), 0, s2>>>(W2, w2h, HID, DIM);
    initout_kernel<<<T_TOK * DIM / 4 / 256, 256, 0, s2>>>(x, out);
    cudaEventRecord(eW2, s2);

    // ---- main stream: routing chain ------------------------------------------
    ln_gate_kernel<<<T_TOK, 256>>>(x, gamma, beta, gate_w);
    scan_kernel<<<1, 256>>>();
    scatter_kernel<<<T_TOK / 256, 256>>>();

    cudaStreamWaitEvent(0, eW1, 0);     // GEMM1 needs w1h
    gemm_mma<1><<<dim3(HID / 128, MAXMT), 256, SMEM_GEMM_BYTES>>>(w1h, b1, nullptr, DIM, HID);

    cudaStreamWaitEvent(0, eW2, 0);     // GEMM2 needs w2h + initialized out
    gemm_mma<2><<<dim3(DIM / 128, MAXMT), 256, SMEM_GEMM_BYTES>>>(w2h, b2, out, HID, DIM);

    loss_kernel<<<1, 256>>>(out, out_size);
}

// round 12
// speedup vs baseline: 1.0351x; 1.0351x over previous
#include <cuda_runtime.h>
#include <cuda_fp16.h>
#include <math.h>
#include <stdint.h>

// Problem constants
#define T_TOK 8192
#define DIM   1024
#define NEXP  8
#define HID   4096
#define MTILE 128
#define MAXROWS 17408            // 16384 + 8*128 pad
#define MAXMT   (MAXROWS / MTILE)

// ---------------- device scratch (static; no cudaMalloc) -------------------
__device__ __half g_xh [(size_t)T_TOK * DIM];      // LN out fp16 (GEMM1 A)
__device__ __half g_hh [(size_t)MAXROWS * HID];    // gelu(x@W1+b1) fp16
__device__ __half g_w1h[(size_t)NEXP * DIM * HID]; // W1 -> [e][n(H)][k(D)] fp16
__device__ __half g_w2h[(size_t)NEXP * HID * DIM]; // W2 -> [e][n(D)][k(H)] fp16
__device__ int    g_perm[MAXROWS];                 // permuted row -> token
__device__ float  g_gwrow[MAXROWS];                // permuted row -> gate weight
__device__ float  g_gw  [T_TOK * 2];
__device__ int    g_gi  [T_TOK * 2];
__device__ int    g_counts[NEXP];
__device__ int    g_off[NEXP + 1];
__device__ int    g_cursor[NEXP];

// ---------------- helpers ----------------------------------------------------
__device__ __forceinline__ void mma_f16(float* c, const unsigned* a, const unsigned* b) {
    asm volatile(
        "mma.sync.aligned.m16n8k16.row.col.f32.f16.f16.f32 "
        "{%0,%1,%2,%3}, {%4,%5,%6,%7}, {%8,%9}, {%0,%1,%2,%3};\n"
        : "+f"(c[0]), "+f"(c[1]), "+f"(c[2]), "+f"(c[3])
        : "r"(a[0]), "r"(a[1]), "r"(a[2]), "r"(a[3]), "r"(b[0]), "r"(b[1]));
}

__device__ __forceinline__ void ldsm_x4(unsigned& r0, unsigned& r1, unsigned& r2, unsigned& r3,
                                        uint32_t addr) {
    asm volatile("ldmatrix.sync.aligned.m8n8.x4.shared.b16 {%0,%1,%2,%3}, [%4];"
        : "=r"(r0), "=r"(r1), "=r"(r2), "=r"(r3) : "r"(addr));
}

__device__ __forceinline__ void cp_async16(uint32_t saddr, const void* gptr) {
    asm volatile("cp.async.cg.shared.global [%0], [%1], 16;"
        :: "r"(saddr), "l"(__cvta_generic_to_global(gptr)) : "memory");
}
#define CP_COMMIT() asm volatile("cp.async.commit_group;" ::: "memory")
#define CP_WAIT2()  asm volatile("cp.async.wait_group 2;"  ::: "memory")
#define CP_WAIT0()  asm volatile("cp.async.wait_group 0;"  ::: "memory")

// ---------------- out = x (residual pre-init for fused combine) -------------
__global__ void initout_kernel(const float* __restrict__ x, float* __restrict__ out) {
    int i = blockIdx.x * blockDim.x + threadIdx.x;
    reinterpret_cast<float4*>(out)[i] = reinterpret_cast<const float4*>(x)[i];
}

// ---------------- weight transpose+fp16: [e][k][n] f32 -> [e][n][k] f16 -----
__global__ void transpose_h_kernel(const float* __restrict__ in, __half* __restrict__ out,
                                   int K, int N) {
    __shared__ float t[32][33];
    const size_t eo = (size_t)blockIdx.z * K * N;
    const int n0 = blockIdx.x * 32, k0 = blockIdx.y * 32;
    for (int j = threadIdx.y; j < 32; j += 8)
        t[j][threadIdx.x] = in[eo + (size_t)(k0 + j) * N + n0 + threadIdx.x];
    __syncthreads();
    for (int j = threadIdx.y; j < 32; j += 8)
        out[eo + (size_t)(n0 + j) * K + k0 + threadIdx.x] = __float2half_rn(t[threadIdx.x][j]);
}

// ---------------- Fused LayerNorm + gating (no global atomics) --------------
__global__ void ln_gate_kernel(const float* __restrict__ x,
                               const float* __restrict__ gamma,
                               const float* __restrict__ beta,
                               const float* __restrict__ gate_w) {
    int t = blockIdx.x;
    int tid = threadIdx.x;
    int lane = tid & 31, wrp = tid >> 5;
    const float4 v = *reinterpret_cast<const float4*>(x + (size_t)t * DIM + tid * 4);
    __shared__ float red1[8], red2[8];
    __shared__ float sgate[8][8];
    __shared__ float slog[8];

    float s = v.x + v.y + v.z + v.w;
    #pragma unroll
    for (int o = 16; o; o >>= 1) s += __shfl_xor_sync(0xffffffffu, s, o);
    if (lane == 0) red1[wrp] = s;
    __syncthreads();
    float mu = 0.f;
    #pragma unroll
    for (int i = 0; i < 8; i++) mu += red1[i];
    mu *= (1.f / DIM);

    float dx = v.x - mu, dy = v.y - mu, dz = v.z - mu, dw = v.w - mu;
    float s2 = dx * dx + dy * dy + dz * dz + dw * dw;
    #pragma unroll
    for (int o = 16; o; o >>= 1) s2 += __shfl_xor_sync(0xffffffffu, s2, o);
    if (lane == 0) red2[wrp] = s2;
    __syncthreads();
    float var = 0.f;
    #pragma unroll
    for (int i = 0; i < 8; i++) var += red2[i];
    var *= (1.f / DIM);
    float rstd = rsqrtf(var + 1e-5f);

    const float4 g = *reinterpret_cast<const float4*>(gamma + tid * 4);
    const float4 b = *reinterpret_cast<const float4*>(beta  + tid * 4);
    float4 o;
    o.x = dx * rstd * g.x + b.x;
    o.y = dy * rstd * g.y + b.y;
    o.z = dz * rstd * g.z + b.z;
    o.w = dw * rstd * g.w + b.w;

    __half2 h0 = __floats2half2_rn(o.x, o.y);
    __half2 h1 = __floats2half2_rn(o.z, o.w);
    *reinterpret_cast<__half2*>(g_xh + (size_t)t * DIM + tid * 4)     = h0;
    *reinterpret_cast<__half2*>(g_xh + (size_t)t * DIM + tid * 4 + 2) = h1;

    float accg[NEXP];
    #pragma unroll
    for (int e = 0; e < NEXP; e++) {
        const float4 w = *reinterpret_cast<const float4*>(gate_w + e * DIM + tid * 4);
        accg[e] = o.x * w.x + o.y * w.y + o.z * w.z + o.w * w.w;
    }
    #pragma unroll
    for (int e = 0; e < NEXP; e++)
        #pragma unroll
        for (int off = 16; off; off >>= 1)
            accg[e] += __shfl_xor_sync(0xffffffffu, accg[e], off);
    if (lane == 0)
        #pragma unroll
        for (int e = 0; e < NEXP; e++) sgate[wrp][e] = accg[e];
    __syncthreads();
    if (tid < NEXP) {
        float l = 0.f;
        #pragma unroll
        for (int w = 0; w < 8; w++) l += sgate[w][tid];
        slog[tid] = l;
    }
    __syncthreads();
    if (tid == 0) {
        int i0 = 0; float v0 = slog[0];
        #pragma unroll
        for (int e = 1; e < NEXP; e++) if (slog[e] > v0) { v0 = slog[e]; i0 = e; }
        int i1 = -1; float v1 = -3.0e38f;
        #pragma unroll
        for (int e = 0; e < NEXP; e++) if (e != i0 && slog[e] > v1) { v1 = slog[e]; i1 = e; }
        float ex = expf(v1 - v0);
        float g0 = 1.f / (1.f + ex);
        float g1 = ex / (1.f + ex);
        g_gi[2 * t]     = i0;  g_gi[2 * t + 1] = i1;
        g_gw[2 * t]     = g0;  g_gw[2 * t + 1] = g1;
    }
}

// ---------------- Scan: histogram g_gi + padded offsets (one block) ---------
__global__ void scan_kernel() {
    __shared__ int cnt[NEXP];
    int tid = threadIdx.x;
    if (tid < NEXP) cnt[tid] = 0;
    __syncthreads();
    for (int i = tid; i < 2 * T_TOK; i += 256)
        atomicAdd(&cnt[g_gi[i]], 1);
    __syncthreads();
    if (tid == 0) {
        int o = 0;
        for (int e = 0; e < NEXP; e++) {
            g_counts[e] = cnt[e];
            g_off[e] = o;
            g_cursor[e] = o;
            o += ((cnt[e] + (MTILE - 1)) / MTILE) * MTILE;
        }
        g_off[NEXP] = o;
    }
}

__global__ void scatter_kernel() {
    int t = blockIdx.x * blockDim.x + threadIdx.x;
    if (t >= T_TOK) return;
    #pragma unroll
    for (int s = 0; s < 2; s++) {
        int e = g_gi[2 * t + s];
        int pos = atomicAdd(&g_cursor[e], 1);
        g_perm[pos]  = t;
        g_gwrow[pos] = g_gw[2 * t + s];
    }
}

// ---------------- Grouped GEMM: fp16 mma m16n8k16 + ldmatrix, 4-stage -------
// Tile 128x128x32, 8 warps (4M x 2N), warp tile 32x64, 4-stage cp.async.
#define NSTAGE 4
#define LSTRIDE 40                       // halves per row (80B)
#define A_STAGE_H (128 * LSTRIDE)
#define B_STAGE_H (128 * LSTRIDE)
#define B_BASE_H  (NSTAGE * A_STAGE_H)
#define SMEM_H    (NSTAGE * A_STAGE_H + NSTAGE * B_STAGE_H)
#define SMEM_GEMM_BYTES (SMEM_H * 2)
#define A_STAGE_B (A_STAGE_H * 2)
#define B_STAGE_B (B_STAGE_H * 2)
#define B_BASE_B  (B_BASE_H * 2)

// MODE 1: A = gather(g_xh, perm) [K=1024], B = g_w1h, C = gelu(.+b1) -> g_hh
// MODE 2: A = g_hh rows          [K=4096], B = g_w2h,
//         C scattered: atomicAdd(out[tok], gate_w * (.+b2))  [fused combine]
template <int MODE>
__global__ void __launch_bounds__(256, 2)
gemm_mma(const __half* __restrict__ Bw, const float* __restrict__ bias,
         float* __restrict__ outp, int Kdim, int Ncols) {
    extern __shared__ __align__(16) __half smh[];

    const int base = blockIdx.y * MTILE;
    if (base >= g_off[NEXP]) return;
    int e = 0;
    while (base >= g_off[e + 1]) e++;
    const int rows_valid = g_off[e] + g_counts[e] - base;
    if (rows_valid <= 0) return;

    const int tid  = threadIdx.x;
    const int lane = tid & 31;
    const int wid  = tid >> 5;
    const int wm = wid & 3;
    const int wn = wid >> 2;
    const int g8   = lane >> 2;
    const int ctid = lane & 3;

    const int ncolbase = blockIdx.x * 128;

    // ---- gmem loaders: 2 threads per row; 2 x 16B segs each per chunk
    const int lrow  = tid >> 1;
    const int lseg  = (tid & 1) * 2;

    const __half* asrc;
    if (MODE == 1) {
        int tok = g_perm[base + lrow];
        if (tok < 0) tok = 0;
        asrc = g_xh + (size_t)tok * DIM;
    } else {
        asrc = g_hh + (size_t)(base + lrow) * HID;
    }
    const __half* bsrc = Bw + ((size_t)e * Ncols + ncolbase + lrow) * Kdim;

    const uint32_t smem_u32 = (uint32_t)__cvta_generic_to_shared(smh);
    const uint32_t a_off0 = lrow * (LSTRIDE * 2) + lseg * 16;
    const uint32_t b_off0 = B_BASE_B + lrow * (LSTRIDE * 2) + lseg * 16;

    // ---- ldmatrix per-thread offsets (bytes)
    const int mq = lane >> 3;
    const int r7 = lane & 7;
    const uint32_t aoff = ((wm * 32 + ((mq & 1) << 3) + r7) * LSTRIDE + ((mq >> 1) << 3)) * 2;
    const uint32_t boff = B_BASE_B +
        ((wn * 64 + ((mq >> 1) << 3) + r7) * LSTRIDE + ((mq & 1) << 3)) * 2;

    float acc[2][8][4];
    #pragma unroll
    for (int i = 0; i < 2; i++)
        #pragma unroll
        for (int j = 0; j < 8; j++)
            #pragma unroll
            for (int q = 0; q < 4; q++) acc[i][j][q] = 0.f;

    const int nch = Kdim / 32;

    // prologue: stage chunks 0..NSTAGE-2
    #pragma unroll
    for (int s = 0; s < NSTAGE - 1; s++) {
        const __half* ga = asrc + s * 32 + lseg * 8;
        const __half* gb = bsrc + s * 32 + lseg * 8;
        const uint32_t ao = smem_u32 + s * A_STAGE_B + a_off0;
        const uint32_t bo = smem_u32 + s * B_STAGE_B + b_off0;
        cp_async16(ao,      ga);
        cp_async16(ao + 16, ga + 8);
        cp_async16(bo,      gb);
        cp_async16(bo + 16, gb + 8);
        CP_COMMIT();
    }

    for (int kc = 0; kc < nch; kc++) {
        CP_WAIT2();
        __syncthreads();

        const int cl = kc + NSTAGE - 1;
        if (cl < nch) {
            const int st2 = cl % NSTAGE;
            const __half* ga = asrc + cl * 32 + lseg * 8;
            const __half* gb = bsrc + cl * 32 + lseg * 8;
            const uint32_t ao = smem_u32 + st2 * A_STAGE_B + a_off0;
            const uint32_t bo = smem_u32 + st2 * B_STAGE_B + b_off0;
            cp_async16(ao,      ga);
            cp_async16(ao + 16, ga + 8);
            cp_async16(bo,      gb);
            cp_async16(bo + 16, gb + 8);
        }
        CP_COMMIT();

        const int st = kc % NSTAGE;
        const uint32_t aBase = smem_u32 + st * A_STAGE_B + aoff;
        const uint32_t bBase = smem_u32 + st * B_STAGE_B + boff;

        #pragma unroll
        for (int ks = 0; ks < 2; ks++) {
            unsigned afr[2][4], bfr[8][2];
            #pragma unroll
            for (int i = 0; i < 2; i++)
                ldsm_x4(afr[i][0], afr[i][1], afr[i][2], afr[i][3],
                        aBase + i * (16 * LSTRIDE * 2) + ks * 32);
            #pragma unroll
            for (int jp = 0; jp < 4; jp++) {
                unsigned r0, r1, r2, r3;
                ldsm_x4(r0, r1, r2, r3, bBase + jp * (16 * LSTRIDE * 2) + ks * 32);
                bfr[2 * jp][0] = r0; bfr[2 * jp][1] = r1;
                bfr[2 * jp + 1][0] = r2; bfr[2 * jp + 1][1] = r3;
            }
            #pragma unroll
            for (int i = 0; i < 2; i++)
                #pragma unroll
                for (int j = 0; j < 8; j++)
                    mma_f16(acc[i][j], afr[i], bfr[j]);
        }
    }
    CP_WAIT0();

    // ---- epilogue (direct fragment stores — R10 proven layout)
    #pragma unroll
    for (int i = 0; i < 2; i++) {
        const int r0 = wm * 32 + i * 16 + g8;
        const int pos0 = base + r0;
        const int pos1 = base + r0 + 8;
        int   tok0 = 0, tok1 = 0;
        float gw0 = 0.f, gw1 = 0.f;
        if (MODE == 2) {
            if (r0 < rows_valid)     { tok0 = g_perm[pos0]; gw0 = g_gwrow[pos0]; }
            if (r0 + 8 < rows_valid) { tok1 = g_perm[pos1]; gw1 = g_gwrow[pos1]; }
        }
        #pragma unroll
        for (int j = 0; j < 8; j++) {
            const int c = wn * 64 + j * 8 + ctid * 2;
            const int ng = ncolbase + c;
            const float bv0 = bias[ng], bv1 = bias[ng + 1];

            if (r0 < rows_valid) {
                float v0 = acc[i][j][0] + bv0;
                float v1 = acc[i][j][1] + bv1;
                if (MODE == 1) {
                    v0 *= normcdff(v0); v1 *= normcdff(v1);
                    *reinterpret_cast<__half2*>(g_hh + (size_t)pos0 * HID + ng) =
                        __floats2half2_rn(v0, v1);
                } else {
                    atomicAdd(&outp[(size_t)tok0 * DIM + ng],     gw0 * v0);
                    atomicAdd(&outp[(size_t)tok0 * DIM + ng + 1], gw0 * v1);
                }
            }
            if (r0 + 8 < rows_valid) {
                float v0 = acc[i][j][2] + bv0;
                float v1 = acc[i][j][3] + bv1;
                if (MODE == 1) {
                    v0 *= normcdff(v0); v1 *= normcdff(v1);
                    *reinterpret_cast<__half2*>(g_hh + (size_t)pos1 * HID + ng) =
                        __floats2half2_rn(v0, v1);
                } else {
                    atomicAdd(&outp[(size_t)tok1 * DIM + ng],     gw1 * v0);
                    atomicAdd(&outp[(size_t)tok1 * DIM + ng + 1], gw1 * v1);
                }
            }
        }
    }
}

// ---------------- Balance loss -------------------------------------------------
__global__ void loss_kernel(float* __restrict__ out, int out_size) {
    __shared__ float red[256];
    __shared__ float tot[NEXP];
    int tid = threadIdx.x;
    float s[NEXP];
    #pragma unroll
    for (int q = 0; q < NEXP; q++) s[q] = 0.f;
    for (int i = tid; i < 2 * T_TOK; i += 256) {
        int e = g_gi[i];
        float w = g_gw[i];
        #pragma unroll
        for (int q = 0; q < NEXP; q++) s[q] += (e == q) ? w : 0.f;
    }
    for (int q = 0; q < NEXP; q++) {
        red[tid] = s[q];
        __syncthreads();
        for (int o = 128; o; o >>= 1) {
            if (tid < o) red[tid] += red[tid + o];
            __syncthreads();
        }
        if (tid == 0) tot[q] = red[0];
        __syncthreads();
    }
    if (tid == 0 && out_size > T_TOK * DIM) {
        float l = 0.f;
        #pragma unroll
        for (int q = 0; q < NEXP; q++) {
            float d = tot[q] * (1.f / T_TOK) - (1.f / NEXP);
            l += d * d;
        }
        out[T_TOK * DIM] = l * (1.f / NEXP);
    }
}

// ---------------- launch --------------------------------------------------------
extern "C" void kernel_launch(void* const* d_in, const int* in_sizes, int n_in,
                              void* d_out, int out_size) {
    const float* x      = (const float*)d_in[0];
    const float* gamma  = (const float*)d_in[1];
    const float* beta   = (const float*)d_in[2];
    const float* gate_w = (const float*)d_in[3];
    const float* W1     = (const float*)d_in[4];
    const float* b1     = (const float*)d_in[5];
    const float* W2     = (const float*)d_in[6];
    const float* b2     = (const float*)d_in[7];
    float* out = (float*)d_out;

    cudaFuncSetAttribute(gemm_mma<1>, cudaFuncAttributeMaxDynamicSharedMemorySize, SMEM_GEMM_BYTES);
    cudaFuncSetAttribute(gemm_mma<2>, cudaFuncAttributeMaxDynamicSharedMemorySize, SMEM_GEMM_BYTES);

    __half *w1h, *w2h;
    cudaGetSymbolAddress((void**)&w1h, g_w1h);
    cudaGetSymbolAddress((void**)&w2h, g_w2h);

    // one-time stream/event setup (no device memory; deterministic)
    static cudaStream_t s2 = nullptr;
    static cudaEvent_t eFork = nullptr, eW1 = nullptr, eW2 = nullptr;
    if (!s2) {
        cudaStreamCreateWithFlags(&s2, cudaStreamNonBlocking);
        cudaEventCreateWithFlags(&eFork, cudaEventDisableTiming);
        cudaEventCreateWithFlags(&eW1,   cudaEventDisableTiming);
        cudaEventCreateWithFlags(&eW2,   cudaEventDisableTiming);
    }

    // ---- fork: weight prep + out-init on side stream ------------------------
    cudaEventRecord(eFork, 0);
    cudaStreamWaitEvent(s2, eFork, 0);
    transpose_h_kernel<<<dim3(HID / 32, DIM / 32, NEXP), dim3(32, 8), 0, s2>>>(W1, w1h, DIM, HID);
    cudaEventRecord(eW1, s2);
    transpose_h_kernel<<<dim3(DIM / 32, HID / 32, NEXP), dim3(32, 8), 0, s2>>>(W2, w2h, HID, DIM);
    initout_kernel<<<T_TOK * DIM / 4 / 256, 256, 0, s2>>>(x, out);
    cudaEventRecord(eW2, s2);

    // ---- main stream: routing chain ------------------------------------------
    ln_gate_kernel<<<T_TOK, 256>>>(x, gamma, beta, gate_w);
    scan_kernel<<<1, 256>>>();
    scatter_kernel<<<T_TOK / 256, 256>>>();

    cudaStreamWaitEvent(0, eW1, 0);     // GEMM1 needs w1h
    gemm_mma<1><<<dim3(HID / 128, MAXMT), 256, SMEM_GEMM_BYTES>>>(w1h, b1, nullptr, DIM, HID);

    cudaStreamWaitEvent(0, eW2, 0);     // GEMM2 needs w2h + initialized out
    gemm_mma<2><<<dim3(DIM / 128, MAXMT), 256, SMEM_GEMM_BYTES>>>(w2h, b2, out, HID, DIM);

    loss_kernel<<<1, 256>>>(out, out_size);
}

// round 13
// speedup vs baseline: 1.0398x; 1.0046x over previous
#include <cuda_runtime.h>
#include <cuda_fp16.h>
#include <math.h>
#include <stdint.h>

// Problem constants
#define T_TOK 8192
#define DIM   1024
#define NEXP  8
#define HID   4096
#define MTILE 128
#define MAXROWS 17408            // 16384 + 8*128 pad
#define MAXMT   (MAXROWS / MTILE)

// ---------------- device scratch (static; no cudaMalloc) -------------------
__device__ __half g_xh [(size_t)T_TOK * DIM];      // LN out fp16 (GEMM1 A)
__device__ __half g_hh [(size_t)MAXROWS * HID];    // gelu(x@W1+b1) fp16
__device__ __half g_w1h[(size_t)NEXP * DIM * HID]; // W1 -> [e][n(H)][k(D)] fp16
__device__ __half g_w2h[(size_t)NEXP * HID * DIM]; // W2 -> [e][n(D)][k(H)] fp16
__device__ int    g_perm[MAXROWS];                 // permuted row -> token
__device__ float  g_gwrow[MAXROWS];                // permuted row -> gate weight
__device__ float  g_gw  [T_TOK * 2];
__device__ int    g_gi  [T_TOK * 2];
__device__ int    g_counts[NEXP];
__device__ int    g_off[NEXP + 1];
__device__ int    g_cursor[NEXP];

// ---------------- helpers ----------------------------------------------------
__device__ __forceinline__ void mma_f16(float* c, const unsigned* a, const unsigned* b) {
    asm volatile(
        "mma.sync.aligned.m16n8k16.row.col.f32.f16.f16.f32 "
        "{%0,%1,%2,%3}, {%4,%5,%6,%7}, {%8,%9}, {%0,%1,%2,%3};\n"
        : "+f"(c[0]), "+f"(c[1]), "+f"(c[2]), "+f"(c[3])
        : "r"(a[0]), "r"(a[1]), "r"(a[2]), "r"(a[3]), "r"(b[0]), "r"(b[1]));
}

__device__ __forceinline__ void ldsm_x4(unsigned& r0, unsigned& r1, unsigned& r2, unsigned& r3,
                                        uint32_t addr) {
    asm volatile("ldmatrix.sync.aligned.m8n8.x4.shared.b16 {%0,%1,%2,%3}, [%4];"
        : "=r"(r0), "=r"(r1), "=r"(r2), "=r"(r3) : "r"(addr));
}

__device__ __forceinline__ void cp_async16(uint32_t saddr, const void* gptr) {
    asm volatile("cp.async.cg.shared.global [%0], [%1], 16;"
        :: "r"(saddr), "l"(__cvta_generic_to_global(gptr)) : "memory");
}
#define CP_COMMIT() asm volatile("cp.async.commit_group;" ::: "memory")
#define CP_WAIT2()  asm volatile("cp.async.wait_group 2;"  ::: "memory")
#define CP_WAIT0()  asm volatile("cp.async.wait_group 0;"  ::: "memory")

// vector f32x2 global reduction (sm_90+): one REDG for two adjacent floats
__device__ __forceinline__ void red_add_v2f32(float* ptr, float v0, float v1) {
    asm volatile("red.global.add.v2.f32 [%0], {%1, %2};"
        :: "l"(__cvta_generic_to_global(ptr)), "f"(v0), "f"(v1) : "memory");
}

// ---------------- out = x (residual pre-init for fused combine) -------------
__global__ void initout_kernel(const float* __restrict__ x, float* __restrict__ out) {
    int i = blockIdx.x * blockDim.x + threadIdx.x;
    reinterpret_cast<float4*>(out)[i] = reinterpret_cast<const float4*>(x)[i];
}

// ---------------- weight transpose+fp16: [e][k][n] f32 -> [e][n][k] f16 -----
__global__ void transpose_h_kernel(const float* __restrict__ in, __half* __restrict__ out,
                                   int K, int N) {
    __shared__ float t[32][33];
    const size_t eo = (size_t)blockIdx.z * K * N;
    const int n0 = blockIdx.x * 32, k0 = blockIdx.y * 32;
    for (int j = threadIdx.y; j < 32; j += 8)
        t[j][threadIdx.x] = in[eo + (size_t)(k0 + j) * N + n0 + threadIdx.x];
    __syncthreads();
    for (int j = threadIdx.y; j < 32; j += 8)
        out[eo + (size_t)(n0 + j) * K + k0 + threadIdx.x] = __float2half_rn(t[threadIdx.x][j]);
}

// ---------------- Fused LayerNorm + gating (no global atomics) --------------
__global__ void ln_gate_kernel(const float* __restrict__ x,
                               const float* __restrict__ gamma,
                               const float* __restrict__ beta,
                               const float* __restrict__ gate_w) {
    int t = blockIdx.x;
    int tid = threadIdx.x;
    int lane = tid & 31, wrp = tid >> 5;
    const float4 v = *reinterpret_cast<const float4*>(x + (size_t)t * DIM + tid * 4);
    __shared__ float red1[8], red2[8];
    __shared__ float sgate[8][8];
    __shared__ float slog[8];

    float s = v.x + v.y + v.z + v.w;
    #pragma unroll
    for (int o = 16; o; o >>= 1) s += __shfl_xor_sync(0xffffffffu, s, o);
    if (lane == 0) red1[wrp] = s;
    __syncthreads();
    float mu = 0.f;
    #pragma unroll
    for (int i = 0; i < 8; i++) mu += red1[i];
    mu *= (1.f / DIM);

    float dx = v.x - mu, dy = v.y - mu, dz = v.z - mu, dw = v.w - mu;
    float s2 = dx * dx + dy * dy + dz * dz + dw * dw;
    #pragma unroll
    for (int o = 16; o; o >>= 1) s2 += __shfl_xor_sync(0xffffffffu, s2, o);
    if (lane == 0) red2[wrp] = s2;
    __syncthreads();
    float var = 0.f;
    #pragma unroll
    for (int i = 0; i < 8; i++) var += red2[i];
    var *= (1.f / DIM);
    float rstd = rsqrtf(var + 1e-5f);

    const float4 g = *reinterpret_cast<const float4*>(gamma + tid * 4);
    const float4 b = *reinterpret_cast<const float4*>(beta  + tid * 4);
    float4 o;
    o.x = dx * rstd * g.x + b.x;
    o.y = dy * rstd * g.y + b.y;
    o.z = dz * rstd * g.z + b.z;
    o.w = dw * rstd * g.w + b.w;

    __half2 h0 = __floats2half2_rn(o.x, o.y);
    __half2 h1 = __floats2half2_rn(o.z, o.w);
    *reinterpret_cast<__half2*>(g_xh + (size_t)t * DIM + tid * 4)     = h0;
    *reinterpret_cast<__half2*>(g_xh + (size_t)t * DIM + tid * 4 + 2) = h1;

    float accg[NEXP];
    #pragma unroll
    for (int e = 0; e < NEXP; e++) {
        const float4 w = *reinterpret_cast<const float4*>(gate_w + e * DIM + tid * 4);
        accg[e] = o.x * w.x + o.y * w.y + o.z * w.z + o.w * w.w;
    }
    #pragma unroll
    for (int e = 0; e < NEXP; e++)
        #pragma unroll
        for (int off = 16; off; off >>= 1)
            accg[e] += __shfl_xor_sync(0xffffffffu, accg[e], off);
    if (lane == 0)
        #pragma unroll
        for (int e = 0; e < NEXP; e++) sgate[wrp][e] = accg[e];
    __syncthreads();
    if (tid < NEXP) {
        float l = 0.f;
        #pragma unroll
        for (int w = 0; w < 8; w++) l += sgate[w][tid];
        slog[tid] = l;
    }
    __syncthreads();
    if (tid == 0) {
        int i0 = 0; float v0 = slog[0];
        #pragma unroll
        for (int e = 1; e < NEXP; e++) if (slog[e] > v0) { v0 = slog[e]; i0 = e; }
        int i1 = -1; float v1 = -3.0e38f;
        #pragma unroll
        for (int e = 0; e < NEXP; e++) if (e != i0 && slog[e] > v1) { v1 = slog[e]; i1 = e; }
        float ex = expf(v1 - v0);
        float g0 = 1.f / (1.f + ex);
        float g1 = ex / (1.f + ex);
        g_gi[2 * t]     = i0;  g_gi[2 * t + 1] = i1;
        g_gw[2 * t]     = g0;  g_gw[2 * t + 1] = g1;
    }
}

// ---------------- Scan: histogram g_gi + padded offsets (one block) ---------
__global__ void scan_kernel() {
    __shared__ int cnt[NEXP];
    int tid = threadIdx.x;
    if (tid < NEXP) cnt[tid] = 0;
    __syncthreads();
    for (int i = tid; i < 2 * T_TOK; i += 256)
        atomicAdd(&cnt[g_gi[i]], 1);
    __syncthreads();
    if (tid == 0) {
        int o = 0;
        for (int e = 0; e < NEXP; e++) {
            g_counts[e] = cnt[e];
            g_off[e] = o;
            g_cursor[e] = o;
            o += ((cnt[e] + (MTILE - 1)) / MTILE) * MTILE;
        }
        g_off[NEXP] = o;
    }
}

__global__ void scatter_kernel() {
    int t = blockIdx.x * blockDim.x + threadIdx.x;
    if (t >= T_TOK) return;
    #pragma unroll
    for (int s = 0; s < 2; s++) {
        int e = g_gi[2 * t + s];
        int pos = atomicAdd(&g_cursor[e], 1);
        g_perm[pos]  = t;
        g_gwrow[pos] = g_gw[2 * t + s];
    }
}

// ---------------- Grouped GEMM: fp16 mma m16n8k16 + ldmatrix, 4-stage -------
// Tile 128x128x32, 8 warps (4M x 2N), warp tile 32x64, 4-stage cp.async.
#define NSTAGE 4
#define LSTRIDE 40                       // halves per row (80B)
#define A_STAGE_H (128 * LSTRIDE)
#define B_STAGE_H (128 * LSTRIDE)
#define B_BASE_H  (NSTAGE * A_STAGE_H)
#define SMEM_H    (NSTAGE * A_STAGE_H + NSTAGE * B_STAGE_H)
#define SMEM_GEMM_BYTES (SMEM_H * 2)
#define A_STAGE_B (A_STAGE_H * 2)
#define B_STAGE_B (B_STAGE_H * 2)
#define B_BASE_B  (B_BASE_H * 2)

// MODE 1: A = gather(g_xh, perm) [K=1024], B = g_w1h, C = gelu(.+b1) -> g_hh
// MODE 2: A = g_hh rows          [K=4096], B = g_w2h,
//         C scattered: red.v2.f32(out[tok], gate_w * (.+b2))  [fused combine]
template <int MODE>
__global__ void __launch_bounds__(256, 2)
gemm_mma(const __half* __restrict__ Bw, const float* __restrict__ bias,
         float* __restrict__ outp, int Kdim, int Ncols) {
    extern __shared__ __align__(16) __half smh[];

    const int base = blockIdx.y * MTILE;
    if (base >= g_off[NEXP]) return;
    int e = 0;
    while (base >= g_off[e + 1]) e++;
    const int rows_valid = g_off[e] + g_counts[e] - base;
    if (rows_valid <= 0) return;

    const int tid  = threadIdx.x;
    const int lane = tid & 31;
    const int wid  = tid >> 5;
    const int wm = wid & 3;
    const int wn = wid >> 2;
    const int g8   = lane >> 2;
    const int ctid = lane & 3;

    const int ncolbase = blockIdx.x * 128;

    // ---- gmem loaders: 2 threads per row; 2 x 16B segs each per chunk
    const int lrow  = tid >> 1;
    const int lseg  = (tid & 1) * 2;

    const __half* asrc;
    if (MODE == 1) {
        int tok = g_perm[base + lrow];
        if (tok < 0) tok = 0;
        asrc = g_xh + (size_t)tok * DIM;
    } else {
        asrc = g_hh + (size_t)(base + lrow) * HID;
    }
    const __half* bsrc = Bw + ((size_t)e * Ncols + ncolbase + lrow) * Kdim;

    const uint32_t smem_u32 = (uint32_t)__cvta_generic_to_shared(smh);
    const uint32_t a_off0 = lrow * (LSTRIDE * 2) + lseg * 16;
    const uint32_t b_off0 = B_BASE_B + lrow * (LSTRIDE * 2) + lseg * 16;

    // ---- ldmatrix per-thread offsets (bytes)
    const int mq = lane >> 3;
    const int r7 = lane & 7;
    const uint32_t aoff = ((wm * 32 + ((mq & 1) << 3) + r7) * LSTRIDE + ((mq >> 1) << 3)) * 2;
    const uint32_t boff = B_BASE_B +
        ((wn * 64 + ((mq >> 1) << 3) + r7) * LSTRIDE + ((mq & 1) << 3)) * 2;

    float acc[2][8][4];
    #pragma unroll
    for (int i = 0; i < 2; i++)
        #pragma unroll
        for (int j = 0; j < 8; j++)
            #pragma unroll
            for (int q = 0; q < 4; q++) acc[i][j][q] = 0.f;

    const int nch = Kdim / 32;

    // prologue: stage chunks 0..NSTAGE-2
    #pragma unroll
    for (int s = 0; s < NSTAGE - 1; s++) {
        const __half* ga = asrc + s * 32 + lseg * 8;
        const __half* gb = bsrc + s * 32 + lseg * 8;
        const uint32_t ao = smem_u32 + s * A_STAGE_B + a_off0;
        const uint32_t bo = smem_u32 + s * B_STAGE_B + b_off0;
        cp_async16(ao,      ga);
        cp_async16(ao + 16, ga + 8);
        cp_async16(bo,      gb);
        cp_async16(bo + 16, gb + 8);
        CP_COMMIT();
    }

    for (int kc = 0; kc < nch; kc++) {
        CP_WAIT2();
        __syncthreads();

        const int cl = kc + NSTAGE - 1;
        if (cl < nch) {
            const int st2 = cl % NSTAGE;
            const __half* ga = asrc + cl * 32 + lseg * 8;
            const __half* gb = bsrc + cl * 32 + lseg * 8;
            const uint32_t ao = smem_u32 + st2 * A_STAGE_B + a_off0;
            const uint32_t bo = smem_u32 + st2 * B_STAGE_B + b_off0;
            cp_async16(ao,      ga);
            cp_async16(ao + 16, ga + 8);
            cp_async16(bo,      gb);
            cp_async16(bo + 16, gb + 8);
        }
        CP_COMMIT();

        const int st = kc % NSTAGE;
        const uint32_t aBase = smem_u32 + st * A_STAGE_B + aoff;
        const uint32_t bBase = smem_u32 + st * B_STAGE_B + boff;

        #pragma unroll
        for (int ks = 0; ks < 2; ks++) {
            unsigned afr[2][4], bfr[8][2];
            #pragma unroll
            for (int i = 0; i < 2; i++)
                ldsm_x4(afr[i][0], afr[i][1], afr[i][2], afr[i][3],
                        aBase + i * (16 * LSTRIDE * 2) + ks * 32);
            #pragma unroll
            for (int jp = 0; jp < 4; jp++) {
                unsigned r0, r1, r2, r3;
                ldsm_x4(r0, r1, r2, r3, bBase + jp * (16 * LSTRIDE * 2) + ks * 32);
                bfr[2 * jp][0] = r0; bfr[2 * jp][1] = r1;
                bfr[2 * jp + 1][0] = r2; bfr[2 * jp + 1][1] = r3;
            }
            #pragma unroll
            for (int i = 0; i < 2; i++)
                #pragma unroll
                for (int j = 0; j < 8; j++)
                    mma_f16(acc[i][j], afr[i], bfr[j]);
        }
    }
    CP_WAIT0();

    // ---- epilogue (direct fragment stores; GEMM2 uses v2 reductions)
    #pragma unroll
    for (int i = 0; i < 2; i++) {
        const int r0 = wm * 32 + i * 16 + g8;
        const int pos0 = base + r0;
        const int pos1 = base + r0 + 8;
        int   tok0 = 0, tok1 = 0;
        float gw0 = 0.f, gw1 = 0.f;
        if (MODE == 2) {
            if (r0 < rows_valid)     { tok0 = g_perm[pos0]; gw0 = g_gwrow[pos0]; }
            if (r0 + 8 < rows_valid) { tok1 = g_perm[pos1]; gw1 = g_gwrow[pos1]; }
        }
        #pragma unroll
        for (int j = 0; j < 8; j++) {
            const int c = wn * 64 + j * 8 + ctid * 2;
            const int ng = ncolbase + c;
            const float bv0 = bias[ng], bv1 = bias[ng + 1];

            if (r0 < rows_valid) {
                float v0 = acc[i][j][0] + bv0;
                float v1 = acc[i][j][1] + bv1;
                if (MODE == 1) {
                    v0 *= normcdff(v0); v1 *= normcdff(v1);
                    *reinterpret_cast<__half2*>(g_hh + (size_t)pos0 * HID + ng) =
                        __floats2half2_rn(v0, v1);
                } else {
                    red_add_v2f32(&outp[(size_t)tok0 * DIM + ng], gw0 * v0, gw0 * v1);
                }
            }
            if (r0 + 8 < rows_valid) {
                float v0 = acc[i][j][2] + bv0;
                float v1 = acc[i][j][3] + bv1;
                if (MODE == 1) {
                    v0 *= normcdff(v0); v1 *= normcdff(v1);
                    *reinterpret_cast<__half2*>(g_hh + (size_t)pos1 * HID + ng) =
                        __floats2half2_rn(v0, v1);
                } else {
                    red_add_v2f32(&outp[(size_t)tok1 * DIM + ng], gw1 * v0, gw1 * v1);
                }
            }
        }
    }
}

// ---------------- Balance loss -------------------------------------------------
__global__ void loss_kernel(float* __restrict__ out, int out_size) {
    __shared__ float red[256];
    __shared__ float tot[NEXP];
    int tid = threadIdx.x;
    float s[NEXP];
    #pragma unroll
    for (int q = 0; q < NEXP; q++) s[q] = 0.f;
    for (int i = tid; i < 2 * T_TOK; i += 256) {
        int e = g_gi[i];
        float w = g_gw[i];
        #pragma unroll
        for (int q = 0; q < NEXP; q++) s[q] += (e == q) ? w : 0.f;
    }
    for (int q = 0; q < NEXP; q++) {
        red[tid] = s[q];
        __syncthreads();
        for (int o = 128; o; o >>= 1) {
            if (tid < o) red[tid] += red[tid + o];
            __syncthreads();
        }
        if (tid == 0) tot[q] = red[0];
        __syncthreads();
    }
    if (tid == 0 && out_size > T_TOK * DIM) {
        float l = 0.f;
        #pragma unroll
        for (int q = 0; q < NEXP; q++) {
            float d = tot[q] * (1.f / T_TOK) - (1.f / NEXP);
            l += d * d;
        }
        out[T_TOK * DIM] = l * (1.f / NEXP);
    }
}

// ---------------- launch --------------------------------------------------------
extern "C" void kernel_launch(void* const* d_in, const int* in_sizes, int n_in,
                              void* d_out, int out_size) {
    const float* x      = (const float*)d_in[0];
    const float* gamma  = (const float*)d_in[1];
    const float* beta   = (const float*)d_in[2];
    const float* gate_w = (const float*)d_in[3];
    const float* W1     = (const float*)d_in[4];
    const float* b1     = (const float*)d_in[5];
    const float* W2     = (const float*)d_in[6];
    const float* b2     = (const float*)d_in[7];
    float* out = (float*)d_out;

    cudaFuncSetAttribute(gemm_mma<1>, cudaFuncAttributeMaxDynamicSharedMemorySize, SMEM_GEMM_BYTES);
    cudaFuncSetAttribute(gemm_mma<2>, cudaFuncAttributeMaxDynamicSharedMemorySize, SMEM_GEMM_BYTES);

    __half *w1h, *w2h;
    cudaGetSymbolAddress((void**)&w1h, g_w1h);
    cudaGetSymbolAddress((void**)&w2h, g_w2h);

    // one-time stream/event setup (no device memory; deterministic)
    static cudaStream_t s2 = nullptr;
    static cudaEvent_t eFork = nullptr, eW1 = nullptr, eW2 = nullptr;
    if (!s2) {
        cudaStreamCreateWithFlags(&s2, cudaStreamNonBlocking);
        cudaEventCreateWithFlags(&eFork, cudaEventDisableTiming);
        cudaEventCreateWithFlags(&eW1,   cudaEventDisableTiming);
        cudaEventCreateWithFlags(&eW2,   cudaEventDisableTiming);
    }

    // ---- fork: weight prep + out-init on side stream ------------------------
    cudaEventRecord(eFork, 0);
    cudaStreamWaitEvent(s2, eFork, 0);
    transpose_h_kernel<<<dim3(HID / 32, DIM / 32, NEXP), dim3(32, 8), 0, s2>>>(W1, w1h, DIM, HID);
    cudaEventRecord(eW1, s2);
    transpose_h_kernel<<<dim3(DIM / 32, HID / 32, NEXP), dim3(32, 8), 0, s2>>>(W2, w2h, HID, DIM);
    initout_kernel<<<T_TOK * DIM / 4 / 256, 256, 0, s2>>>(x, out);
    cudaEventRecord(eW2, s2);

    // ---- main stream: routing chain ------------------------------------------
    ln_gate_kernel<<<T_TOK, 256>>>(x, gamma, beta, gate_w);
    scan_kernel<<<1, 256>>>();
    scatter_kernel<<<T_TOK / 256, 256>>>();

    cudaStreamWaitEvent(0, eW1, 0);     // GEMM1 needs w1h
    gemm_mma<1><<<dim3(HID / 128, MAXMT), 256, SMEM_GEMM_BYTES>>>(w1h, b1, nullptr, DIM, HID);

    cudaStreamWaitEvent(0, eW2, 0);     // GEMM2 needs w2h + initialized out
    gemm_mma<2><<<dim3(DIM / 128, MAXMT), 256, SMEM_GEMM_BYTES>>>(w2h, b2, out, HID, DIM);

    loss_kernel<<<1, 256>>>(out, out_size);
}